// round 6
// baseline (speedup 1.0000x reference)
#include <cuda_runtime.h>
#include <cuda_bf16.h>
#include <cstdint>

// SIR SDE: 8192 trajectories x 4900 effective steps, sampled every 100 steps (49 samples),
// features: max, (argmax+u)/49, std(diff(log x)).
//
// R6: ILP-2. Per-warp measurements showed ~55 cyc/step against a ~27-cyc r0 dependency
// chain -> the single chain leaves issue bubbles ptxas can't fill. Two independent
// trajectories per thread interleave their chains and fill each other's MUFU shadows.
// 128 blocks x 32 threads (one warp per SM), thread handles trajectories b and b+4096.
// dW streamed via cp.async 3-buffer pipeline, 20-step chunks, both 128-B segments/row.

#define BSZ    8192
#define HALF   4096
#define CH     20             // steps per chunk; 100 % CH == 0
#define NCHUNK 245            // 4900 effective steps
#define CHUNK_BYTES (CH * 256)          // 20 rows x 2 segs x 128 B = 5120 B
#define CHUNK_FLOATS (CH * 64)

__device__ __forceinline__ void cp_async16(uint32_t saddr, const void* gptr) {
    asm volatile("cp.async.ca.shared.global [%0], [%1], 16;" :: "r"(saddr), "l"(gptr));
}
__device__ __forceinline__ void cp_commit() {
    asm volatile("cp.async.commit_group;");
}
template <int N>
__device__ __forceinline__ void cp_wait() {
    asm volatile("cp.async.wait_group %0;" :: "n"(N));
}
__device__ __forceinline__ float sqrt_approx(float x) {
    float r;
    asm("sqrt.approx.f32 %0, %1;" : "=f"(r) : "f"(x));
    return r;
}

__global__ __launch_bounds__(32, 1)
void sir_sde_kernel(const float* __restrict__ cond,
                    const float* __restrict__ dW,
                    const float* __restrict__ u,
                    float* __restrict__ out)
{
    __shared__ float sdw[3 * CHUNK_FLOATS];   // 3 bufs x 20 rows x (2 segs x 32 lanes)

    const int lane = threadIdx.x & 31;
    const int b0   = blockIdx.x * 32;         // first trajectory of segment 0
    const int bA   = b0 + lane;               // chain A trajectory
    const int bB   = bA + HALF;               // chain B trajectory

    // ---------- per-trajectory parameters (two chains) ----------
    float omA, c1A, kvolA, ndtrecA, omrA, r0A, qA, iA;
    float omB, c1B, kvolB, ndtrecB, omrB, r0B, qB, iB;
    const float DT  = 0.01f;
    const float sdt = sqrtf(DT);
    {
        const float ir = cond[bA * 4 + 0], rc = cond[bA * 4 + 1];
        const float mr = cond[bA * 4 + 2], vl = cond[bA * 4 + 3];
        const float r0i = __fdiv_rn(ir, rc);
        const float dtmr = DT * mr;
        omA = 1.0f - dtmr;  c1A = dtmr * r0i;  kvolA = vl * sdt;
        ndtrecA = -DT * rc; omrA = 1.0f + ndtrecA;
        r0A = r0i; qA = rc * 0.99f; iA = 0.01f;
    }
    {
        const float ir = cond[bB * 4 + 0], rc = cond[bB * 4 + 1];
        const float mr = cond[bB * 4 + 2], vl = cond[bB * 4 + 3];
        const float r0i = __fdiv_rn(ir, rc);
        const float dtmr = DT * mr;
        omB = 1.0f - dtmr;  c1B = dtmr * r0i;  kvolB = vl * sdt;
        ndtrecB = -DT * rc; omrB = 1.0f + ndtrecB;
        r0B = r0i; qB = rc * 0.99f; iB = 0.01f;
    }

    // ---------- feature accumulators ----------
    float maxA = -3.402823466e38f, maxB = -3.402823466e38f;
    int   argA = 0, argB = 0;
    float plgA = 0.0f, plgB = 0.0f;
    float sdA = 0.0f, sd2A = 0.0f, sdB = 0.0f, sd2B = 0.0f;

    // ---------- cp.async chunk copier ----------
    // chunk c, row r (global step c*CH+r): seg0 = dW + (c*CH+r)*BSZ + b0 (128 B),
    // seg1 = same + HALF. smem layout: buf + r*256 + seg*128 + lane*4.
    uint32_t smem_base;
    asm("{ .reg .u64 t; cvta.to.shared.u64 t, %1; cvt.u32.u64 %0, t; }"
        : "=r"(smem_base) : "l"(sdw));

    const char* gbase = (const char*)(dW + b0);

    auto issue_chunk = [&](int c, int bufidx) {
        const char* g = gbase + (size_t)c * CH * BSZ * 4;
        uint32_t sb = smem_base + bufidx * CHUNK_BYTES;
#pragma unroll
        for (int i = 0; i < 10; ++i) {
            int f   = i * 512 + lane * 16;      // flat byte offset in buffer (0..5104)
            int row = f >> 8;                   // /256
            int rem = f & 255;
            int seg = rem >> 7;                 // 0 or 1
            int col = rem & 127;
            cp_async16(sb + f, g + (size_t)row * BSZ * 4 + seg * (HALF * 4) + col);
        }
        cp_commit();
    };

    issue_chunk(0, 0);
    issue_chunk(1, 1);

#pragma unroll 1
    for (int c = 0; c < NCHUNK; ++c) {
        // Tail: fewer than 2 groups pending -> wait<1> would not cover chunk c.
        if (c >= NCHUNK - 2) cp_wait<0>();
        else                 cp_wait<1>();
        __syncwarp();

        // burst-copy chunk c to registers (conflict-free LDS)
        float dwv[2 * CH];
        const float* sp = sdw + (c % 3) * CHUNK_FLOATS + lane;
#pragma unroll
        for (int k = 0; k < CH; ++k) {
            dwv[2 * k + 0] = sp[k * 64];        // seg 0 (chain A)
            dwv[2 * k + 1] = sp[k * 64 + 32];   // seg 1 (chain B)
        }

        if (c + 2 < NCHUNK) issue_chunk(c + 2, (c + 2) % 3);

        // ---------- 20 Euler-Maruyama steps, two interleaved chains ----------
#pragma unroll
        for (int k = 0; k < CH; ++k) {
            // chain A
            const float c2A = dwv[2 * k + 0] * kvolA;
            const float niA = r0A * qA;
            const float sqA = sqrt_approx(fabsf(r0A));
            const float tA  = fmaf(r0A, omA, c1A);
            // chain B (independent; fills A's MUFU shadow)
            const float c2B = dwv[2 * k + 1] * kvolB;
            const float niB = r0B * qB;
            const float sqB = sqrt_approx(fabsf(r0B));
            const float tB  = fmaf(r0B, omB, c1B);

            r0A = fmaf(sqA, c2A, tA);
            qA  = fmaf(niA, ndtrecA, qA);
            iA  = fmaf(DT, niA, iA * omrA);

            r0B = fmaf(sqB, c2B, tB);
            qB  = fmaf(niB, ndtrecB, qB);
            iB  = fmaf(DT, niB, iB * omrB);
        }

        // ---------- sample after steps 99, 199, ..., 4899 ----------
        if (c % 5 == 4) {
            const int j = c / 5;
            float xA = iA;
            if ((__float_as_uint(xA) & 0x7f800000u) == 0x7f800000u) xA = 0.0f;
            xA = fmaxf(xA, 1e-5f);
            if (xA > maxA) { maxA = xA; argA = j; }
            const float lgA = logf(xA);
            if (j > 0) { const float d = lgA - plgA; sdA += d; sd2A += d * d; }
            plgA = lgA;

            float xB = iB;
            if ((__float_as_uint(xB) & 0x7f800000u) == 0x7f800000u) xB = 0.0f;
            xB = fmaxf(xB, 1e-5f);
            if (xB > maxB) { maxB = xB; argB = j; }
            const float lgB = logf(xB);
            if (j > 0) { const float d = lgB - plgB; sdB += d; sd2B += d * d; }
            plgB = lgB;
        }
    }

    // ---------- features ----------
    {
        const float max_at = ((float)argA + u[bA]) / 49.0f;
        const float mean   = sdA * (1.0f / 48.0f);
        float var = sd2A * (1.0f / 48.0f) - mean * mean;
        var = fmaxf(var, 0.0f);
        out[bA * 3 + 0] = maxA;
        out[bA * 3 + 1] = max_at;
        out[bA * 3 + 2] = sqrtf(var);
    }
    {
        const float max_at = ((float)argB + u[bB]) / 49.0f;
        const float mean   = sdB * (1.0f / 48.0f);
        float var = sd2B * (1.0f / 48.0f) - mean * mean;
        var = fmaxf(var, 0.0f);
        out[bB * 3 + 0] = maxB;
        out[bB * 3 + 1] = max_at;
        out[bB * 3 + 2] = sqrtf(var);
    }
}

extern "C" void kernel_launch(void* const* d_in, const int* in_sizes, int n_in,
                              void* d_out, int out_size)
{
    const float* cond = (const float*)d_in[0];   // (8192, 4)
    const float* dW   = (const float*)d_in[1];   // (5000, 8192)
    const float* u    = (const float*)d_in[2];   // (8192,)
    float* out        = (float*)d_out;           // (8192, 3)

    sir_sde_kernel<<<HALF / 32, 32>>>(cond, dW, u, out);
}